// round 6
// baseline (speedup 1.0000x reference)
#include <cuda_runtime.h>
#include <cuda_bf16.h>
#include <cstdint>
#include <cstddef>

#define DEVI __device__ __forceinline__

constexpr int MAX_M = 8192, MAX_N = 4096, MAX_K = 4096;

__device__ unsigned char g_Xq[(size_t)MAX_M * MAX_K];   // uint8 activations
__device__ signed char   g_Wq[(size_t)MAX_N * MAX_K];   // int8 weights
__device__ float g_xs[MAX_M], g_xz[MAX_M], g_ws[MAX_N], g_wrs[MAX_N];

DEVI uint32_t smem_u32(const void* p) {
    uint32_t a;
    asm("{ .reg .u64 t; cvta.to.shared.u64 t, %1; cvt.u32.u64 %0, t; }" : "=r"(a) : "l"(p));
    return a;
}
DEVI void cp16(uint32_t s, const void* g) {
    asm volatile("cp.async.cg.shared.global [%0], [%1], 16;" :: "r"(s), "l"(g));
}
DEVI void ldsm_x4(uint32_t& r0, uint32_t& r1, uint32_t& r2, uint32_t& r3, uint32_t a) {
    asm volatile("ldmatrix.sync.aligned.m8n8.x4.shared.b16 {%0,%1,%2,%3}, [%4];"
                 : "=r"(r0), "=r"(r1), "=r"(r2), "=r"(r3) : "r"(a));
}
DEVI void mma_u8s8(int* c, uint32_t a0, uint32_t a1, uint32_t a2, uint32_t a3,
                   uint32_t b0, uint32_t b1) {
    asm volatile(
        "mma.sync.aligned.m16n8k32.row.col.s32.u8.s8.s32 "
        "{%0,%1,%2,%3}, {%4,%5,%6,%7}, {%8,%9}, {%0,%1,%2,%3};"
        : "+r"(c[0]), "+r"(c[1]), "+r"(c[2]), "+r"(c[3])
        : "r"(a0), "r"(a1), "r"(a2), "r"(a3), "r"(b0), "r"(b1));
}

// ---------------- quantization: weights (1 block / row) ----------------
__global__ void __launch_bounds__(256) quant_w_kernel(const float* __restrict__ W, int K) {
    const int n = blockIdx.x, tid = threadIdx.x;
    const float4* w4 = reinterpret_cast<const float4*>(W + (size_t)n * K);
    float4 v[4]; float am = 0.f;
#pragma unroll
    for (int j = 0; j < 4; j++) {
        v[j] = w4[j * 256 + tid];
        am = fmaxf(am, fmaxf(fmaxf(fabsf(v[j].x), fabsf(v[j].y)), fmaxf(fabsf(v[j].z), fabsf(v[j].w))));
    }
    __shared__ float sred[8]; __shared__ float s_scale;
    for (int o = 16; o; o >>= 1) am = fmaxf(am, __shfl_xor_sync(~0u, am, o));
    if ((tid & 31) == 0) sred[tid >> 5] = am;
    __syncthreads();
    if (tid == 0) {
        float m2 = sred[0];
        for (int i = 1; i < 8; i++) m2 = fmaxf(m2, sred[i]);
        float sc = (m2 > 0.f) ? m2 * (1.0f / 127.0f) : 1.0f;
        s_scale = sc; g_ws[n] = sc;
    }
    __syncthreads();
    const float sc = s_scale; float rs = 0.f;
    char4* o4 = reinterpret_cast<char4*>(g_Wq + (size_t)n * K);
#pragma unroll
    for (int j = 0; j < 4; j++) {
        float q0 = fminf(fmaxf(rintf(v[j].x / sc), -127.f), 127.f);
        float q1 = fminf(fmaxf(rintf(v[j].y / sc), -127.f), 127.f);
        float q2 = fminf(fmaxf(rintf(v[j].z / sc), -127.f), 127.f);
        float q3 = fminf(fmaxf(rintf(v[j].w / sc), -127.f), 127.f);
        rs += (q0 + q1) + (q2 + q3);
        o4[j * 256 + tid] = make_char4((signed char)q0, (signed char)q1,
                                       (signed char)q2, (signed char)q3);
    }
    for (int o = 16; o; o >>= 1) rs += __shfl_xor_sync(~0u, rs, o);
    __syncthreads();
    if ((tid & 31) == 0) sred[tid >> 5] = rs;
    __syncthreads();
    if (tid == 0) {
        float t = 0.f;
        for (int i = 0; i < 8; i++) t += sred[i];
        g_wrs[n] = t;
    }
}

// ---------------- quantization: activations (1 block / token) ----------------
__global__ void __launch_bounds__(256) quant_x_kernel(const float* __restrict__ X, int K) {
    const int m = blockIdx.x, tid = threadIdx.x;
    const float4* x4 = reinterpret_cast<const float4*>(X + (size_t)m * K);
    float4 v[4]; float mn = 3.4e38f, mx = -3.4e38f;
#pragma unroll
    for (int j = 0; j < 4; j++) {
        v[j] = x4[j * 256 + tid];
        mn = fminf(mn, fminf(fminf(v[j].x, v[j].y), fminf(v[j].z, v[j].w)));
        mx = fmaxf(mx, fmaxf(fmaxf(v[j].x, v[j].y), fmaxf(v[j].z, v[j].w)));
    }
    __shared__ float smn[8], smx[8]; __shared__ float s_sc, s_zp;
    for (int o = 16; o; o >>= 1) {
        mn = fminf(mn, __shfl_xor_sync(~0u, mn, o));
        mx = fmaxf(mx, __shfl_xor_sync(~0u, mx, o));
    }
    if ((tid & 31) == 0) { smn[tid >> 5] = mn; smx[tid >> 5] = mx; }
    __syncthreads();
    if (tid == 0) {
        float a = smn[0], b = smx[0];
        for (int i = 1; i < 8; i++) { a = fminf(a, smn[i]); b = fmaxf(b, smx[i]); }
        float rng = b - a;
        float sc = (rng > 0.f) ? rng * (1.0f / 255.0f) : 1.0f;
        s_sc = sc; s_zp = rintf(-a / sc);
        g_xs[m] = sc; g_xz[m] = s_zp;
    }
    __syncthreads();
    const float sc = s_sc, zp = s_zp;
    uchar4* o4 = reinterpret_cast<uchar4*>(g_Xq + (size_t)m * K);
#pragma unroll
    for (int j = 0; j < 4; j++) {
        float q0 = fminf(fmaxf(rintf(v[j].x / sc) + zp, 0.f), 255.f);
        float q1 = fminf(fmaxf(rintf(v[j].y / sc) + zp, 0.f), 255.f);
        float q2 = fminf(fmaxf(rintf(v[j].z / sc) + zp, 0.f), 255.f);
        float q3 = fminf(fmaxf(rintf(v[j].w / sc) + zp, 0.f), 255.f);
        o4[j * 256 + tid] = make_uchar4((unsigned char)q0, (unsigned char)q1,
                                        (unsigned char)q2, (unsigned char)q3);
    }
}

// ---------------- GEMM: int8 mma.sync, 128x128 CTA tile, K-chunk 128 ----------------
constexpr int TM = 128, TN = 128, KC = 128, GT = 256, STAGES = 3;
constexpr uint32_t A_BYTES = (uint32_t)TM * KC;          // 16 KB
constexpr uint32_t STG_BYTES = A_BYTES + (uint32_t)TN * KC; // 32 KB
constexpr uint32_t SMEM_GEMM = STAGES * STG_BYTES;       // 96 KB

DEVI uint32_t swz(uint32_t row, uint32_t c16) {   // byte offset within a 128B-row tile
    return row * 128u + ((c16 ^ (row & 7u)) << 4);
}

__global__ void __launch_bounds__(GT, 2) gemm_kernel(
    const float* __restrict__ bias, float* __restrict__ Y, int M, int N, int K)
{
    extern __shared__ char smem[];
    const uint32_t sb = smem_u32(smem);
    const int tid = threadIdx.x, wid = tid >> 5, lane = tid & 31;
    const int n0 = blockIdx.x * TN, m0 = blockIdx.y * TM;
    const int wm = (wid & 1) * 64;        // warp m offset (2 warps in M)
    const int wn = (wid >> 1) * 32;       // warp n offset (4 warps in N)

    // per-thread fill coords: row = tid>>1 (0..127), half = tid&1 (64B each)
    const int frow = tid >> 1, fhalf = tid & 1;
    const char* Ag = reinterpret_cast<const char*>(g_Xq) + (size_t)(m0 + frow) * K + fhalf * 64;
    const char* Bg = reinterpret_cast<const char*>(g_Wq) + (size_t)(n0 + frow) * K + fhalf * 64;
    const int NITER = K / KC;

    auto fill = [&](int s, int kk) {
        const uint32_t sA = sb + (uint32_t)s * STG_BYTES;
        const uint32_t sB = sA + A_BYTES;
        const char* ap = Ag + (size_t)kk * KC;
        const char* bp = Bg + (size_t)kk * KC;
#pragma unroll
        for (int j = 0; j < 4; j++) {
            const uint32_t o = swz((uint32_t)frow, (uint32_t)(fhalf * 4 + j));
            cp16(sA + o, ap + j * 16);
            cp16(sB + o, bp + j * 16);
        }
        asm volatile("cp.async.commit_group;");
    };

    fill(0, 0);
    fill(1, 1);

    int acc[4][4][4];   // [m-tile][n-tile][frag]
#pragma unroll
    for (int a = 0; a < 4; a++)
#pragma unroll
        for (int b = 0; b < 4; b++)
#pragma unroll
            for (int c = 0; c < 4; c++) acc[a][b][c] = 0;

    // ldmatrix lane coords (constant across iterations)
    const uint32_t a_row = (uint32_t)(wm + (lane & 15));       // + mt*16
    const uint32_t a_chi = (uint32_t)(lane >> 4);              // + ks*2
    const uint32_t b_row = (uint32_t)(wn + ((lane >> 4) << 3) + (lane & 7)); // + nt2*16
    const uint32_t b_chi = (uint32_t)((lane >> 3) & 1);        // + ks*2

    for (int i = 0; i < NITER; i++) {
        const int s = i % STAGES;
        if (i + 1 < NITER) asm volatile("cp.async.wait_group 1;" ::: "memory");
        else               asm volatile("cp.async.wait_group 0;" ::: "memory");
        __syncthreads();

        const uint32_t sA = sb + (uint32_t)s * STG_BYTES;
        const uint32_t sB = sA + A_BYTES;
#pragma unroll
        for (int ks = 0; ks < 4; ks++) {
            uint32_t a[4][4];
#pragma unroll
            for (int mt = 0; mt < 4; mt++)
                ldsm_x4(a[mt][0], a[mt][1], a[mt][2], a[mt][3],
                        sA + swz(a_row + mt * 16u, (uint32_t)ks * 2u + a_chi));
            uint32_t b[4][2];
#pragma unroll
            for (int nt2 = 0; nt2 < 2; nt2++) {
                uint32_t r0, r1, r2, r3;
                ldsm_x4(r0, r1, r2, r3,
                        sB + swz(b_row + nt2 * 16u, (uint32_t)ks * 2u + b_chi));
                b[nt2 * 2][0] = r0; b[nt2 * 2][1] = r1;
                b[nt2 * 2 + 1][0] = r2; b[nt2 * 2 + 1][1] = r3;
            }
#pragma unroll
            for (int mt = 0; mt < 4; mt++)
#pragma unroll
                for (int nt = 0; nt < 4; nt++)
                    mma_u8s8(acc[mt][nt], a[mt][0], a[mt][1], a[mt][2], a[mt][3],
                             b[nt][0], b[nt][1]);
        }
        __syncthreads();
        const int c = i + 2;
        if (c < NITER) fill(c % STAGES, c);
    }

    // ---- epilogue: exact s32 accum -> fused dequant + bias ----
    const int g = lane >> 2, tg = lane & 3;
#pragma unroll
    for (int mt = 0; mt < 4; mt++) {
        const int r0 = m0 + wm + mt * 16 + g;
        const int r1 = r0 + 8;
        const float sa0 = g_xs[r0], zp0 = g_xz[r0];
        const float sa1 = g_xs[r1], zp1 = g_xz[r1];
#pragma unroll
        for (int nt = 0; nt < 4; nt++) {
            const int cn = n0 + wn + nt * 8 + tg * 2;
            const float ws0 = g_ws[cn],  ws1 = g_ws[cn + 1];
            const float wr0 = g_wrs[cn], wr1 = g_wrs[cn + 1];
            const float bi0 = bias[cn],  bi1 = bias[cn + 1];
            float2 y0, y1;
            y0.x = fmaf(sa0 * ws0, (float)acc[mt][nt][0] - zp0 * wr0, bi0);
            y0.y = fmaf(sa0 * ws1, (float)acc[mt][nt][1] - zp0 * wr1, bi1);
            y1.x = fmaf(sa1 * ws0, (float)acc[mt][nt][2] - zp1 * wr0, bi0);
            y1.y = fmaf(sa1 * ws1, (float)acc[mt][nt][3] - zp1 * wr1, bi1);
            *reinterpret_cast<float2*>(Y + (size_t)r0 * N + cn) = y0;
            *reinterpret_cast<float2*>(Y + (size_t)r1 * N + cn) = y1;
        }
    }
}

extern "C" void kernel_launch(void* const* d_in, const int* in_sizes, int n_in,
                              void* d_out, int out_size) {
    const float* x = (const float*)d_in[0];
    const float* w = (const float*)d_in[1];
    const float* bias = (const float*)d_in[2];
    const int N = in_sizes[2];
    const int K = in_sizes[1] / N;
    const int M = in_sizes[0] / K;
    quant_w_kernel<<<N, 256>>>(w, K);
    quant_x_kernel<<<M, 256>>>(x, K);
    cudaFuncSetAttribute(gemm_kernel, cudaFuncAttributeMaxDynamicSharedMemorySize, SMEM_GEMM);
    gemm_kernel<<<dim3(N / TN, M / TM), GT, SMEM_GEMM>>>(bias, (float*)d_out, M, N, K);
}